// round 16
// baseline (speedup 1.0000x reference)
#include <cuda_runtime.h>
#include <math.h>

#define BN 8
#define NN 131072
#define NBLK 64
#define TPB 256
#define CHUNK (NN / NBLK)      // 2048
#define PPT (CHUNK / TPB)      // 8
#define NSUM 84                // 36 Bm + 6 V + 36 Hsc + 6 bsc
#define SPLITK 16
#define CHN (NN / SPLITK)      // 8192 points per split chunk

#define MULR(a,b) __fmul_rn((a),(b))
#define ADDR_(a,b) __fadd_rn((a),(b))
#define SUBR(a,b) __fsub_rn((a),(b))
#define DIVR(a,b) __fdiv_rn((a),(b))
#define SQRTR(a)  __fsqrt_rn((a))
#define FMAR(a,b,c) __fmaf_rn((a),(b),(c))

// ---------------- scratch ----------------
__device__ float g_disp[2][BN][NN];
__device__ float g_posecur[BN][16];
__device__ float g_posecand[BN][16];
__device__ float g_L[BN];
__device__ float g_invL[BN];
__device__ float g_dp[BN][6];
__device__ int   g_cur[BN];
__device__ float g_sums[BN][NSUM];
__device__ float g_part2[BN][NBLK][2];

// per-point field buffer, SoA [field][b][n]
// fields: 0-5 A0, 6-11 A1, 12 ex, 13 ey, 14 w, 15 w2, 16-21 E, 22 cinv, 23 Wv
__device__ float g_pt[24][BN][NN];

struct BC {
    float k00,k01,k02,k10,k11,k12,k20,k21,k22;
    float i00,i01,i02,i10,i11,i12,i20,i21,i22;
    float r00,r01,r02,t0, r10,r11,r12,t1, r20,r21,r22,t2;
};

__device__ __forceinline__ void load_bc(BC& bc, int b,
        const float* __restrict__ K, const float* __restrict__ Ki,
        const float* __restrict__ P)
{
    const float* k = K + b*9; const float* ki = Ki + b*9;
    bc.k00=k[0]; bc.k01=k[1]; bc.k02=k[2];
    bc.k10=k[3]; bc.k11=k[4]; bc.k12=k[5];
    bc.k20=k[6]; bc.k21=k[7]; bc.k22=k[8];
    bc.i00=ki[0]; bc.i01=ki[1]; bc.i02=ki[2];
    bc.i10=ki[3]; bc.i11=ki[4]; bc.i12=ki[5];
    bc.i20=ki[6]; bc.i21=ki[7]; bc.i22=ki[8];
    bc.r00=P[0]; bc.r01=P[1]; bc.r02=P[2]; bc.t0=P[3];
    bc.r10=P[4]; bc.r11=P[5]; bc.r12=P[6]; bc.t1=P[7];
    bc.r20=P[8]; bc.r21=P[9]; bc.r22=P[10]; bc.t2=P[11];
}

// p3d = (K_inv @ [x;y;1]) / disp; fma gemm chains.
__device__ __forceinline__ void project_chain_div(const BC& bc,
        float x1, float y1, float disp_div,
        float& X, float& Y, float& Z, float& u, float& v)
{
    float hx = ADDR_(FMAR(bc.i01, y1, MULR(bc.i00, x1)), bc.i02);
    float hy = ADDR_(FMAR(bc.i11, y1, MULR(bc.i10, x1)), bc.i12);
    float hz = ADDR_(FMAR(bc.i21, y1, MULR(bc.i20, x1)), bc.i22);
    float px = DIVR(hx, disp_div), py = DIVR(hy, disp_div), pz = DIVR(hz, disp_div);
    X = ADDR_(FMAR(bc.r02, pz, FMAR(bc.r01, py, MULR(bc.r00, px))), bc.t0);
    Y = ADDR_(FMAR(bc.r12, pz, FMAR(bc.r11, py, MULR(bc.r10, px))), bc.t1);
    Z = ADDR_(FMAR(bc.r22, pz, FMAR(bc.r21, py, MULR(bc.r20, px))), bc.t2);
    float qx = FMAR(bc.k02, Z, FMAR(bc.k01, Y, MULR(bc.k00, X)));
    float qy = FMAR(bc.k12, Z, FMAR(bc.k11, Y, MULR(bc.k10, X)));
    float qz = FMAR(bc.k22, Z, FMAR(bc.k21, Y, MULR(bc.k20, X)));
    float qzc = fmaxf(qz, 0.01f);
    u = DIVR(qx, qzc);
    v = DIVR(qy, qzc);
}

__device__ __forceinline__ void point_core(const BC& bc,
        float x1, float y1, float x2, float y2, float d, float m,
        float& ex, float& ey, float A0[6], float A1[6],
        float& g0, float& g1, float& w, float& w2)
{
    float X, Y, Z, u, v;
    project_chain_div(bc, x1, y1, d, X, Y, Z, u, v);
    ex = SUBR(x2, u);
    ey = SUBR(y2, v);

    float Zc  = fmaxf(Z, 1e-12f);
    float iZ  = DIVR(1.0f, Zc);
    float iZ2 = MULR(iZ, iZ);
    float fx = bc.k00, fy = bc.k11;
    float nfx = -fx, nfy = -fy;
    A0[0] = MULR(fx, iZ);
    A0[1] = 0.0f;
    A0[2] = MULR(MULR(nfx, X), iZ2);
    A0[3] = MULR(MULR(MULR(nfx, X), Y), iZ2);
    A0[4] = ADDR_(fx, MULR(MULR(MULR(fx, X), X), iZ2));
    A0[5] = MULR(MULR(nfx, Y), iZ);
    A1[0] = 0.0f;
    A1[1] = MULR(fy, iZ);
    A1[2] = MULR(MULR(nfy, Y), iZ2);
    A1[3] = SUBR(nfy, MULR(MULR(MULR(fy, Y), Y), iZ2));
    A1[4] = MULR(MULR(MULR(fy, X), Y), iZ2);
    A1[5] = MULR(MULR(fy, X), iZ);

    float DD = -DIVR(1.0f, d);
    float J2x = MULR(DD, SUBR(X, bc.t0));
    float J2y = MULR(SUBR(Y, bc.t1), DD);
    float J2z = MULR(SUBR(Zc, bc.t2), DD);
    g0 = FMAR(A0[2], J2z, MULR(A0[0], J2x));
    g1 = FMAR(A1[2], J2z, MULR(A1[1], J2y));

    float en = SQRTR(ADDR_(MULR(ex, ex), MULR(ey, ey)));
    float wv = fminf(DIVR(9.0f, fmaxf(en, 1e-12f)), 1.0f);
    w  = MULR(SQRTR(wv), m);
    w2 = MULR(w, w);
}

__device__ __forceinline__ void point_ECW(const float A0[6], const float A1[6],
        float g0, float g1, float ex, float ey, float w, float w2, float Lb,
        float E[6], float& cinv, float& Wv)
{
#pragma unroll
    for (int i = 0; i < 6; i++)
        E[i] = FMAR(MULR(w2, A1[i]), g1, MULR(MULR(w2, A0[i]), g0));
    float C  = FMAR(MULR(w2, g1), g1, MULR(MULR(w2, g0), g0));
    float Cc = ADDR_(C, MULR(C, Lb));
    cinv = DIVR(1.0f, fmaxf(Cc, 1.0f));
    Wv = FMAR(MULR(w, g1), ey, MULR(MULR(w, g0), ex));
}

// ---------------------------------------------------------------------------
__global__ void __launch_bounds__(TPB) phaseA_kernel(
        const float* __restrict__ pc, const float* __restrict__ mask,
        const float* __restrict__ K, const float* __restrict__ Ki)
{
    int b = blockIdx.x / NBLK, blk = blockIdx.x % NBLK;
    BC bc; load_bc(bc, b, K, Ki, g_posecur[b]);
    float Lb = g_L[b];
    const float* dptr = g_disp[g_cur[b]][b];
    const float* p1x = pc + (size_t)(b*4 + 0)*NN;
    const float* p1y = pc + (size_t)(b*4 + 1)*NN;
    const float* p2x = pc + (size_t)(b*4 + 2)*NN;
    const float* p2y = pc + (size_t)(b*4 + 3)*NN;
    const float* mptr = mask + (size_t)b*NN;

    int base = blk*CHUNK + threadIdx.x;
#pragma unroll
    for (int k = 0; k < PPT; k++) {
        int n = base + k*TPB;
        float ex, ey, g0, g1, w, w2;
        float A0[6], A1[6];
        point_core(bc, p1x[n], p1y[n], p2x[n], p2y[n], dptr[n], mptr[n],
                   ex, ey, A0, A1, g0, g1, w, w2);
        float E[6], cinv, Wv;
        point_ECW(A0, A1, g0, g1, ex, ey, w, w2, Lb, E, cinv, Wv);

#pragma unroll
        for (int i = 0; i < 6; i++) g_pt[i][b][n] = A0[i];
#pragma unroll
        for (int i = 0; i < 6; i++) g_pt[6+i][b][n] = A1[i];
        g_pt[12][b][n] = ex;
        g_pt[13][b][n] = ey;
        g_pt[14][b][n] = w;
        g_pt[15][b][n] = w2;
#pragma unroll
        for (int i = 0; i < 6; i++) g_pt[16+i][b][n] = E[i];
        g_pt[22][b][n] = cinv;
        g_pt[23][b][n] = Wv;
    }
}

// ---------------------------------------------------------------------------
// Phase B: cuBLAS fp32 splitK model. Per output element:
//   SPLITK=16 CONTIGUOUS chunks of 8192 points; each chunk summed by ONE
//   serial ascending fp32 FMA chain with a single accumulator (cutlass-SIMT
//   mainloop), k-minor flat order for Bm/V (two fma per point, k=0 then k=1);
//   chunk partials combined in ascending split order, fp32.
__global__ void __launch_bounds__(SPLITK) phaseB_kernel()
{
    int b = blockIdx.x / NSUM;
    int q = blockIdx.x % NSUM;
    int t = threadIdx.x;          // split index 0..15
    int n0 = t * CHN;
    int nend = n0 + CHN;

    float acc = 0.0f;
    if (q < 36) {
        int i = q / 6, j = q % 6;
        const float* fa0i = g_pt[i][b];
        const float* fa0j = g_pt[j][b];
        const float* fa1i = g_pt[6+i][b];
        const float* fa1j = g_pt[6+j][b];
        const float* fw2  = g_pt[15][b];
        for (int n = n0; n < nend; n++) {
            float w2 = fw2[n];
            acc = FMAR(MULR(w2, fa0i[n]), fa0j[n], acc);
            acc = FMAR(MULR(w2, fa1i[n]), fa1j[n], acc);
        }
    } else if (q < 42) {
        int i = q - 36;
        const float* fa0i = g_pt[i][b];
        const float* fa1i = g_pt[6+i][b];
        const float* fex  = g_pt[12][b];
        const float* fey  = g_pt[13][b];
        const float* fw   = g_pt[14][b];
        for (int n = n0; n < nend; n++) {
            float w = fw[n];
            acc = FMAR(MULR(w, fa0i[n]), fex[n], acc);
            acc = FMAR(MULR(w, fa1i[n]), fey[n], acc);
        }
    } else if (q < 78) {
        int tt = q - 42;
        int i = tt / 6, j = tt % 6;
        const float* fei = g_pt[16+i][b];
        const float* fej = g_pt[16+j][b];
        const float* fci = g_pt[22][b];
        for (int n = n0; n < nend; n++)
            acc = FMAR(MULR(fci[n], fei[n]), fej[n], acc);
    } else {
        int i = q - 78;
        const float* fei = g_pt[16+i][b];
        const float* fci = g_pt[22][b];
        const float* fwv = g_pt[23][b];
        for (int n = n0; n < nend; n++)
            acc = FMAR(fei[n], MULR(fci[n], fwv[n]), acc);
    }

    __shared__ float part[SPLITK];
    part[t] = acc;
    __syncthreads();
    if (t == 0) {
        float tot = part[0];
        for (int s = 1; s < SPLITK; s++) tot = ADDR_(tot, part[s]);
        g_sums[b][q] = tot;
    }
}

// ---------------------------------------------------------------------------
// Marginalization + solve + SE3 + compose in DOUBLE.
__global__ void solve_kernel()
{
    int b = blockIdx.x;
    if (threadIdx.x != 0) return;

    double invN = 1.0 / 131072.0;
    float Lf = g_L[b];
    double L = (double)Lf;
    double invL = 1.0 / (1.0 + L);

    double Bm[6][6], Hs[6][6], V[6], bs[6];
    for (int i = 0; i < 6; i++)
        for (int j = 0; j < 6; j++) Bm[i][j] = (double)g_sums[b][i*6+j]*invN;
    for (int i = 0; i < 6; i++) V[i] = (double)g_sums[b][36+i]*invN;
    for (int i = 0; i < 6; i++)
        for (int j = 0; j < 6; j++) Hs[i][j] = (double)g_sums[b][42+i*6+j]*invN;
    for (int i = 0; i < 6; i++) bs[i] = (double)g_sums[b][78+i]*invN;

    for (int i = 0; i < 6; i++) Bm[i][i] = Bm[i][i]*(1.0 + L) + 1.0;

    double A[6][7], sc[6];
    for (int i = 0; i < 6; i++)
        for (int j = 0; j < 6; j++) A[i][j] = Bm[i][j] - Hs[i][j]*invL;
    for (int i = 0; i < 6; i++) sc[i] = 1.0 / sqrt(A[i][i] + 10.0);
    for (int i = 0; i < 6; i++) {
        for (int j = 0; j < 6; j++) A[i][j] *= sc[i]*sc[j];
        A[i][6] = (V[i] - bs[i]*invL) * sc[i];
    }
    for (int k = 0; k < 6; k++) {
        int piv = k; double mx = fabs(A[k][k]);
        for (int i = k+1; i < 6; i++) if (fabs(A[i][k]) > mx) { mx = fabs(A[i][k]); piv = i; }
        if (piv != k)
            for (int j = 0; j < 7; j++) { double tv = A[k][j]; A[k][j] = A[piv][j]; A[piv][j] = tv; }
        double ik = 1.0 / A[k][k];
        for (int i = k+1; i < 6; i++) {
            double f = A[i][k]*ik;
            for (int j = k; j < 7; j++) A[i][j] -= f*A[k][j];
        }
    }
    double x[6];
    for (int i = 5; i >= 0; i--) {
        double s = A[i][6];
        for (int j = i+1; j < 6; j++) s -= A[i][j]*x[j];
        x[i] = s / A[i][i];
    }
    double dp[6];
    for (int i = 0; i < 6; i++) { dp[i] = sc[i]*x[i]; g_dp[b][i] = (float)dp[i]; }
    g_invL[b] = DIVR(1.0f, ADDR_(1.0f, Lf));

    double tx = dp[0], ty = dp[1], tz = dp[2];
    double wx = dp[3], wy = dp[4], wz = dp[5];
    double Nr = sqrt(wx*wx + wy*wy + wz*wz);
    if (Nr < 1e-12) Nr = 1e-12;
    double rx = wx/Nr, ry = wy/Nr, rz = wz/Nr;
    double cN = cos(Nr), sN = sin(Nr);
    double oc = 1.0 - cN;
    double R[3][3];
    R[0][0] = cN + oc*rx*rx;  R[0][1] = oc*rx*ry - sN*rz;  R[0][2] = oc*rx*rz + sN*ry;
    R[1][0] = oc*ry*rx + sN*rz;  R[1][1] = cN + oc*ry*ry;  R[1][2] = oc*ry*rz - sN*rx;
    R[2][0] = oc*rz*rx - sN*ry;  R[2][1] = oc*rz*ry + sN*rx;  R[2][2] = cN + oc*rz*rz;
    double k1 = (Nr - sN)/Nr, k2 = oc/Nr;
    double sk[3][3] = {{0,-rz,ry},{rz,0,-rx},{-ry,rx,0}};
    double Jm[3][3];
    for (int i = 0; i < 3; i++)
        for (int j = 0; j < 3; j++) {
            double skk = sk[i][0]*sk[0][j] + sk[i][1]*sk[1][j] + sk[i][2]*sk[2][j];
            double idn = (i == j) ? 1.0 : 0.0;
            Jm[i][j] = idn + k1*skk + k2*sk[i][j];
        }
    double T[3];
    for (int i = 0; i < 3; i++) T[i] = Jm[i][0]*tx + Jm[i][1]*ty + Jm[i][2]*tz;

    const float* P = g_posecur[b];
    float* C = g_posecand[b];
    for (int i = 0; i < 3; i++)
        for (int j = 0; j < 4; j++)
            C[i*4+j] = (float)(R[i][0]*(double)P[0*4+j] + R[i][1]*(double)P[1*4+j]
                             + R[i][2]*(double)P[2*4+j] + T[i]*(double)P[3*4+j]);
    for (int j = 0; j < 4; j++) C[12+j] = P[12+j];
}

// ---------------------------------------------------------------------------
__global__ void __launch_bounds__(TPB) pass2_kernel(
        const float* __restrict__ pc, const float* __restrict__ mask,
        const float* __restrict__ K, const float* __restrict__ Ki)
{
    int b = blockIdx.x / NBLK, blk = blockIdx.x % NBLK;
    BC bc; load_bc(bc, b, K, Ki, g_posecur[b]);
    BC bcc; load_bc(bcc, b, K, Ki, g_posecand[b]);
    float Lb = g_L[b];
    float invL = g_invL[b];
    float dp[6];
#pragma unroll
    for (int i = 0; i < 6; i++) dp[i] = g_dp[b][i];

    int cur = g_cur[b];
    const float* dptr = g_disp[cur][b];
    float* dnew = g_disp[1 - cur][b];
    const float* p1x = pc + (size_t)(b*4 + 0)*NN;
    const float* p1y = pc + (size_t)(b*4 + 1)*NN;
    const float* p2x = pc + (size_t)(b*4 + 2)*NN;
    const float* p2y = pc + (size_t)(b*4 + 3)*NN;
    const float* mptr = mask + (size_t)b*NN;

    float s1 = 0.0f, s2 = 0.0f;
    int base = blk*CHUNK + threadIdx.x;
#pragma unroll
    for (int k = 0; k < PPT; k++) {
        int n = base + k*TPB;
        float x1 = p1x[n], y1 = p1y[n], x2 = p2x[n], y2 = p2y[n];
        float d = dptr[n], m = mptr[n];
        float ex, ey, g0, g1, w, w2;
        float A0[6], A1[6];
        point_core(bc, x1, y1, x2, y2, d, m, ex, ey, A0, A1, g0, g1, w, w2);
        float E[6], cinv, Wv;
        point_ECW(A0, A1, g0, g1, ex, ey, w, w2, Lb, E, cinv, Wv);

        float edp = MULR(E[0], dp[0]);
        edp = FMAR(E[1], dp[1], edp);
        edp = FMAR(E[2], dp[2], edp);
        edp = FMAR(E[3], dp[3], edp);
        edp = FMAR(E[4], dp[4], edp);
        edp = FMAR(E[5], dp[5], edp);
        float p3dsc = MULR(edp, invL);
        float dd = MULR(cinv, SUBR(Wv, p3dsc));
        float dn = fminf(fmaxf(ADDR_(d, dd), 0.01f), 10.0f);
        dnew[n] = dn;

        float X, Y, Z, u, v;
        project_chain_div(bcc, x1, y1, fmaxf(dn, 0.01f), X, Y, Z, u, v);
        float e1x = SUBR(x2, u);
        float e1y = SUBR(y2, v);
        s1 += MULR(SQRTR(ADDR_(MULR(e1x,e1x), MULR(e1y,e1y))), m);
        s2 += MULR(SQRTR(ADDR_(MULR(ex,ex), MULR(ey,ey))), m);
    }

#pragma unroll
    for (int off = 16; off; off >>= 1) {
        s1 += __shfl_down_sync(0xffffffffu, s1, off);
        s2 += __shfl_down_sync(0xffffffffu, s2, off);
    }
    __shared__ float sh1[TPB/32], sh2[TPB/32];
    int lane = threadIdx.x & 31, wid = threadIdx.x >> 5;
    if (lane == 0) { sh1[wid] = s1; sh2[wid] = s2; }
    __syncthreads();
    if (threadIdx.x == 0) {
        float a = 0.0f, bsum = 0.0f;
#pragma unroll
        for (int wv = 0; wv < TPB/32; wv++) { a += sh1[wv]; bsum += sh2[wv]; }
        g_part2[b][blk][0] = a;
        g_part2[b][blk][1] = bsum;
    }
}

// ---------------------------------------------------------------------------
__global__ void decide_kernel()
{
    int b = blockIdx.x;
    if (threadIdx.x != 0) return;
    double s1 = 0.0, s2 = 0.0;
    for (int k = 0; k < NBLK; k++) { s1 += (double)g_part2[b][k][0]; s2 += (double)g_part2[b][k][1]; }
    float D = 131072.0f;
    float r1 = DIVR((float)s1, D);
    float r2 = DIVR((float)s2, D);
    bool M = (r1 < r2);
    float L = g_L[b];
    float Lnew = M ? MULR(L, 0.5f) : MULR(L, 5.0f);
    g_L[b] = fminf(fmaxf(Lnew, 0.01f), 1000000.0f);
    if (M) {
        g_cur[b] ^= 1;
        for (int j = 0; j < 16; j++) g_posecur[b][j] = g_posecand[b][j];
    }
}

// ---------------------------------------------------------------------------
__global__ void init_kernel(const float* __restrict__ disp_in,
                            const float* __restrict__ pose_in,
                            const float* __restrict__ L_in)
{
    int tid = blockIdx.x*blockDim.x + threadIdx.x;
    for (int i = tid; i < BN*NN; i += gridDim.x*blockDim.x) {
        g_disp[0][i / NN][i % NN] = disp_in[i];
    }
    if (tid < BN*16) g_posecur[tid/16][tid%16] = pose_in[tid];
    if (tid < BN) { g_L[tid] = L_in[tid]; g_cur[tid] = 0; }
}

__global__ void final_kernel(float* __restrict__ out)
{
    int tid = blockIdx.x*blockDim.x + threadIdx.x;
    int total = 128 + BN*NN;
    for (int i = tid; i < total; i += gridDim.x*blockDim.x) {
        if (i < 128) {
            out[i] = g_posecur[i/16][i%16];
        } else {
            int j = i - 128;
            int b = j / NN, n = j % NN;
            out[i] = g_disp[g_cur[b]][b][n];
        }
    }
}

// ---------------------------------------------------------------------------
extern "C" void kernel_launch(void* const* d_in, const int* in_sizes, int n_in,
                              void* d_out, int out_size)
{
    const float* pc   = (const float*)d_in[0];
    const float* disp = (const float*)d_in[1];
    const float* pose = (const float*)d_in[2];
    const float* K    = (const float*)d_in[3];
    const float* Ki   = (const float*)d_in[4];
    const float* mask = (const float*)d_in[5];
    const float* L    = (const float*)d_in[6];

    init_kernel<<<512, 256>>>(disp, pose, L);
    for (int it = 0; it < 4; it++) {
        phaseA_kernel<<<BN*NBLK, TPB>>>(pc, mask, K, Ki);
        phaseB_kernel<<<BN*NSUM, SPLITK>>>();
        solve_kernel<<<BN, 32>>>();
        pass2_kernel<<<BN*NBLK, TPB>>>(pc, mask, K, Ki);
        decide_kernel<<<BN, 32>>>();
    }
    final_kernel<<<1024, 256>>>((float*)d_out);
}